// round 9
// baseline (speedup 1.0000x reference)
#include <cuda_runtime.h>
#include <cstdint>

// ============================================================================
// OctonionHeadMixer == one 32768 x 1024 x 1024 GEMM (WEIGHT_IDX[i][j] = i^j):
//   y[b,i,t,e] = sum_{j,d} x[b,j,t,d] * (sign[i,j] * W[i^j][d,e] * beta[e])
//
// compute_100 (non-"a") => portable tensor-core path:
//   mma.sync.aligned.m16n8k8.row.col.f32.tf32.tf32.f32
//
// R8 (338.9us, tensor=73.5%) -> R9: spread the per-chunk cp.async burst.
//   The 16 cp.async per thread (rt~8cyc) used to issue right after the
//   barrier, idling the tensor pipe ~150-200 cyc per chunk. Now:
//     sync -> MMAs(ks=0) -> cp.async A-half -> MMAs(ks=1) -> cp.async B-half
//     + commit -> MMAs(ks=2,3)
//   so the LSU burst issues while the tensor pipe drains queued MMAs.
//   Group accounting identical (1 commit per iteration, group idx == chunk).
// ============================================================================

#define DEVINL __device__ __forceinline__

static constexpr int KT       = 32;        // K chunks of 32 (1024 total)
static constexpr int STAGES   = 3;
static constexpr uint32_t STAGE_BYTES = 32768;   // A 16KB + B 16KB
static constexpr uint32_t SMEM_TOTAL  = STAGES * STAGE_BYTES;  // 96 KB

__device__ __constant__ signed char d_sign[64] = {
  +1,-1,-1,-1,-1,-1,-1,-1,
  +1,+1,+1,-1,+1,-1,-1,+1,
  +1,-1,+1,+1,+1,+1,-1,-1,
  +1,+1,-1,+1,+1,-1,+1,-1,
  +1,-1,-1,-1,+1,+1,+1,+1,
  +1,+1,-1,+1,-1,+1,-1,+1,
  +1,+1,+1,-1,-1,+1,+1,-1,
  +1,-1,+1,+1,-1,-1,+1,+1
};

// Combined weights in B-fragment order, tf32 bits. 4 MB device scratch.
// Layout: [kstep(128)][nblock(128)][lane(32)][h(2)]
//   value(h) = M[n = nblock*8 + (lane>>2)][k = kstep*8 + (lane&3) + 4*h]
__device__ __align__(256) uint32_t g_WG[1024u * 1024u];

// ---------------- helpers ----------------
DEVINL uint32_t smem_u32(const void* p) {
    uint32_t a;
    asm("{ .reg .u64 t; cvta.to.shared.u64 t, %1; cvt.u32.u64 %0, t; }" : "=r"(a) : "l"(p));
    return a;
}
DEVINL void cp16(uint32_t dst, const void* src) {
    asm volatile("cp.async.cg.shared.global [%0], [%1], 16;" :: "r"(dst), "l"(src) : "memory");
}
DEVINL void cp_commit() { asm volatile("cp.async.commit_group;" ::: "memory"); }
DEVINL uint32_t lds32(uint32_t a) {
    uint32_t v; asm volatile("ld.shared.b32 %0, [%1];" : "=r"(v) : "r"(a)); return v;
}
DEVINL void lds64(uint32_t& x, uint32_t& y, uint32_t a) {
    asm volatile("ld.shared.v2.b32 {%0, %1}, [%2];" : "=r"(x), "=r"(y) : "r"(a));
}
DEVINL void mma16n8k8(float* c, const uint32_t* a, const uint32_t* b) {
    asm volatile(
        "mma.sync.aligned.m16n8k8.row.col.f32.tf32.tf32.f32 "
        "{%0,%1,%2,%3}, {%4,%5,%6,%7}, {%8,%9}, {%0,%1,%2,%3};"
        : "+f"(c[0]), "+f"(c[1]), "+f"(c[2]), "+f"(c[3])
        : "r"(a[0]), "r"(a[1]), "r"(a[2]), "r"(a[3]), "r"(b[0]), "r"(b[1]));
}

// ---------------- prep: build combined weights in fragment order ----------------
__global__ void octo_prep(const float* __restrict__ W, const float* __restrict__ beta) {
    const uint32_t idx = blockIdx.x * blockDim.x + threadIdx.x;  // 0 .. 2^20-1
    const uint32_t w     = idx & 63u;       // within 64-value fragment block
    const uint32_t blk   = idx >> 6;        // kstep*128 + nblock
    const uint32_t kstep = blk >> 7;
    const uint32_t nblk  = blk & 127u;
    const uint32_t lane  = w >> 1, h = w & 1u;
    const uint32_t n = nblk * 8 + (lane >> 2);
    const uint32_t k = kstep * 8 + (lane & 3) + 4 * h;
    const uint32_t i = n >> 7, e = n & 127u, j = k >> 7, d = k & 127u;
    const float v = W[((((i ^ j) << 7) | d) << 7) | e]
                    * (float)d_sign[(i << 3) | j] * beta[e];
    uint32_t t;
    asm("cvt.rna.tf32.f32 %0, %1;" : "=r"(t) : "f"(v));
    g_WG[idx] = t;
}

// ---------------- main GEMM ----------------
__global__ void __launch_bounds__(128, 2)
octo_gemm(const float* __restrict__ x, float* __restrict__ out)
{
    extern __shared__ __align__(16) float sm[];
    const uint32_t sbase = smem_u32(sm);
    const int tid   = threadIdx.x;
    const int wid   = tid >> 5;
    const int lane  = tid & 31;
    const int warpM = wid & 1;        // 2 warps over M (64 rows each)
    const int warpN = wid >> 1;       // 2 warps over N (64 cols each)
    const int tig   = lane & 3;       // thread-in-group (k)
    const int grp   = lane >> 2;      // group (m/n row)

    const int ntile = blockIdx.x;           // 0..7  == output head i
    const int mt_   = blockIdx.y;           // 0..255
    const int b     = mt_ >> 5;
    const int t0    = (mt_ & 31) << 7;

    const float* wgf = (const float*)g_WG;

    // ---- stage loader halves: A (XOR-swizzled) and B (fragment-order) ----
    auto loadA = [&](int kt, int slot) {
        const int j  = kt >> 2;
        const int d0 = (kt & 3) << 5;
        const float* xa = x + ((((size_t)(b * 8 + j)) * 4096 + t0) << 7) + d0;
        const uint32_t abase = sbase + slot * STAGE_BYTES;
        #pragma unroll
        for (int q = 0; q < 8; ++q) {
            const int c  = q * 128 + tid;
            const int m  = c >> 3;
            const int k4 = c & 7;
            cp16(abase + m * 128 + ((k4 ^ (m & 7)) << 4),
                 xa + (size_t)m * 128 + k4 * 4);
        }
    };
    auto loadB = [&](int kt, int slot) {
        const uint32_t bbase = sbase + slot * STAGE_BYTES + 16384;
        #pragma unroll
        for (int ks = 0; ks < 4; ++ks) {
            #pragma unroll
            for (int h = 0; h < 2; ++h) {
                const int c = h * 128 + tid;   // 0..255 chunks of 16B = 4KB
                cp16(bbase + ks * 4096 + c * 16,
                     wgf + (((size_t)(kt * 4 + ks) * 128 + ntile * 16) << 6) + c * 4);
            }
        }
    };

    float acc[4][8][4];
    #pragma unroll
    for (int a = 0; a < 4; ++a)
        #pragma unroll
        for (int c = 0; c < 8; ++c)
            #pragma unroll
            for (int q = 0; q < 4; ++q) acc[a][c][q] = 0.0f;

    loadA(0, 0); loadB(0, 0); cp_commit();
    loadA(1, 1); loadB(1, 1); cp_commit();

    // Per-thread invariant pieces of the fragment addresses.
    const uint32_t swz = (uint32_t)(grp & 7);
    const uint32_t a_thread = (uint32_t)((warpM * 64 + grp) * 128 + tig * 4);
    const uint32_t b_thread = (uint32_t)(lane * 8);

    #pragma unroll 1
    for (int kt = 0; kt < KT; ++kt) {
        asm volatile("cp.async.wait_group 1;" ::: "memory");
        __syncthreads();
        const int slot = kt % 3;
        const uint32_t abase = sbase + slot * STAGE_BYTES + a_thread;
        const uint32_t bbase = sbase + slot * STAGE_BYTES + 16384 + b_thread;
        const int nkt = kt + STAGES - 1;      // chunk to prefetch
        const int nslot = nkt % 3;            // == (kt-1)%3, barrier-proven free

        #pragma unroll
        for (int ks = 0; ks < 4; ++ks) {
            const uint32_t ch0 = ((uint32_t)(2 * ks)     ^ swz) << 4;
            const uint32_t ch1 = ((uint32_t)(2 * ks + 1) ^ swz) << 4;
            uint32_t arg[4][4];
            #pragma unroll
            for (int mt = 0; mt < 4; ++mt) {
                const uint32_t r0 = abase + mt * (16 * 128) + ch0;
                const uint32_t r2 = abase + mt * (16 * 128) + ch1;
                arg[mt][0] = lds32(r0);
                arg[mt][1] = lds32(r0 + 8 * 128);
                arg[mt][2] = lds32(r2);
                arg[mt][3] = lds32(r2 + 8 * 128);
            }
            uint32_t brg[8][2];
            #pragma unroll
            for (int nt = 0; nt < 8; ++nt) {
                const uint32_t addr = bbase + (uint32_t)((ks * 16 + warpN * 8 + nt) * 256);
                lds64(brg[nt][0], brg[nt][1], addr);
            }
            #pragma unroll
            for (int mt = 0; mt < 4; ++mt)
                #pragma unroll
                for (int nt = 0; nt < 8; ++nt)
                    mma16n8k8(acc[mt][nt], arg[mt], brg[nt]);

            // Spread the cp.async burst into the tensor-pipe backlog:
            // A-half after ks=0, B-half (+commit) after ks=1.
            if (ks == 0 && nkt < KT) loadA(nkt, nslot);
            if (ks == 1) {
                if (nkt < KT) loadB(nkt, nslot);
                cp_commit();                  // exactly one group per iteration
            }
        }
    }

    // ---- epilogue: registers -> gmem (head = ntile, e contiguous) ----
    const size_t obase = (((size_t)(b * 8 + ntile)) * 4096 + t0) << 7;
    #pragma unroll
    for (int mt = 0; mt < 4; ++mt) {
        const int r0 = warpM * 64 + mt * 16 + grp;
        #pragma unroll
        for (int nt = 0; nt < 8; ++nt) {
            const int e0 = warpN * 64 + nt * 8 + tig * 2;
            float2* p0 = (float2*)(out + obase + (size_t)r0 * 128 + e0);
            float2* p1 = (float2*)(out + obase + (size_t)(r0 + 8) * 128 + e0);
            *p0 = make_float2(acc[mt][nt][0], acc[mt][nt][1]);
            *p1 = make_float2(acc[mt][nt][2], acc[mt][nt][3]);
        }
    }
}

// ---------------- host ----------------
extern "C" void kernel_launch(void* const* d_in, const int* in_sizes, int n_in,
                              void* d_out, int out_size)
{
    const float* x    = (const float*)d_in[0];
    const float* W    = (const float*)d_in[1];
    const float* beta = (const float*)d_in[2];

    // 1) fold signs + beta into fragment-ordered combined weights (tf32 RN)
    octo_prep<<<4096, 256>>>(W, beta);

    // 2) GEMM: grid = (8 head-tiles, 256 row-tiles), 96 KB smem, 2 CTAs/SM.
    cudaFuncSetAttribute(octo_gemm, cudaFuncAttributeMaxDynamicSharedMemorySize,
                         (int)SMEM_TOTAL);
    dim3 grid(8, 256, 1);
    octo_gemm<<<grid, 128, SMEM_TOTAL>>>(x, (float*)d_out);
}

// round 12
// speedup vs baseline: 1.0845x; 1.0845x over previous
#include <cuda_runtime.h>
#include <cstdint>

// ============================================================================
// OctonionHeadMixer == one 32768 x 1024 x 1024 GEMM (WEIGHT_IDX[i][j] = i^j):
//   y[b,i,t,e] = sum_{j,d} x[b,j,t,d] * (sign[i,j] * W[i^j][d,e] * beta[e])
//
// compute_100 (non-"a") => portable tensor-core path:
//   mma.sync.aligned.m16n8k8.row.col.f32.tf32.tf32.f32
//
// R8 339us/tensor 73.5%. Measured: m16n8k8 rt ~8.3cyc -> floor 261us; the
// 26% tensor idle = windows where BOTH resident warps (1 per CTA, 2/SMSP)
// are in load phases. This kernel:
//   * ldmatrix.m8n8.x4.b16 loads a full m16-tile A fragment in ONE instr
//     (8x8 fp32 == 8x16 b16; b16 pair fragment == whole b32 tf32 fragment):
//     per-chunk LDS issues 96 -> 48.
//   * explicit ks+1 fragment double-buffer in registers: MMA stream only
//     waits on LDS at chunk entry, not at every ks.
//   * pipeline structure (3-stage, 1 sync/chunk, group==chunk) identical R8.
// ============================================================================

#define DEVINL __device__ __forceinline__

static constexpr int KT       = 32;        // K chunks of 32 (1024 total)
static constexpr int STAGES   = 3;
static constexpr uint32_t STAGE_BYTES = 32768;   // A 16KB + B 16KB
static constexpr uint32_t SMEM_TOTAL  = STAGES * STAGE_BYTES;  // 96 KB

__device__ __constant__ signed char d_sign[64] = {
  +1,-1,-1,-1,-1,-1,-1,-1,
  +1,+1,+1,-1,+1,-1,-1,+1,
  +1,-1,+1,+1,+1,+1,-1,-1,
  +1,+1,-1,+1,+1,-1,+1,-1,
  +1,-1,-1,-1,+1,+1,+1,+1,
  +1,+1,-1,+1,-1,+1,-1,+1,
  +1,+1,+1,-1,-1,+1,+1,-1,
  +1,-1,+1,+1,-1,-1,+1,+1
};

// Combined weights in B-fragment order, tf32 bits. 4 MB device scratch.
// Layout: [kstep(128)][nblock(128)][lane(32)][h(2)]
//   value(h) = M[n = nblock*8 + (lane>>2)][k = kstep*8 + (lane&3) + 4*h]
__device__ __align__(256) uint32_t g_WG[1024u * 1024u];

// ---------------- helpers ----------------
DEVINL uint32_t smem_u32(const void* p) {
    uint32_t a;
    asm("{ .reg .u64 t; cvta.to.shared.u64 t, %1; cvt.u32.u64 %0, t; }" : "=r"(a) : "l"(p));
    return a;
}
DEVINL void cp16(uint32_t dst, const void* src) {
    asm volatile("cp.async.cg.shared.global [%0], [%1], 16;" :: "r"(dst), "l"(src) : "memory");
}
DEVINL void cp_commit() { asm volatile("cp.async.commit_group;" ::: "memory"); }
DEVINL void lds64(uint32_t& x, uint32_t& y, uint32_t a) {
    asm volatile("ld.shared.v2.b32 {%0, %1}, [%2];" : "=r"(x), "=r"(y) : "r"(a));
}
DEVINL void ldsm_x4(uint32_t* r, uint32_t a) {
    asm volatile("ldmatrix.sync.aligned.m8n8.x4.shared.b16 {%0,%1,%2,%3}, [%4];"
                 : "=r"(r[0]), "=r"(r[1]), "=r"(r[2]), "=r"(r[3]) : "r"(a));
}
DEVINL void mma16n8k8(float* c, const uint32_t* a, const uint32_t* b) {
    asm volatile(
        "mma.sync.aligned.m16n8k8.row.col.f32.tf32.tf32.f32 "
        "{%0,%1,%2,%3}, {%4,%5,%6,%7}, {%8,%9}, {%0,%1,%2,%3};"
        : "+f"(c[0]), "+f"(c[1]), "+f"(c[2]), "+f"(c[3])
        : "r"(a[0]), "r"(a[1]), "r"(a[2]), "r"(a[3]), "r"(b[0]), "r"(b[1]));
}

// ---------------- prep: build combined weights in fragment order ----------------
__global__ void octo_prep(const float* __restrict__ W, const float* __restrict__ beta) {
    const uint32_t idx = blockIdx.x * blockDim.x + threadIdx.x;  // 0 .. 2^20-1
    const uint32_t w     = idx & 63u;       // within 64-value fragment block
    const uint32_t blk   = idx >> 6;        // kstep*128 + nblock
    const uint32_t kstep = blk >> 7;
    const uint32_t nblk  = blk & 127u;
    const uint32_t lane  = w >> 1, h = w & 1u;
    const uint32_t n = nblk * 8 + (lane >> 2);
    const uint32_t k = kstep * 8 + (lane & 3) + 4 * h;
    const uint32_t i = n >> 7, e = n & 127u, j = k >> 7, d = k & 127u;
    const float v = W[((((i ^ j) << 7) | d) << 7) | e]
                    * (float)d_sign[(i << 3) | j] * beta[e];
    uint32_t t;
    asm("cvt.rna.tf32.f32 %0, %1;" : "=r"(t) : "f"(v));
    g_WG[idx] = t;
}

// ---------------- main GEMM ----------------
__global__ void __launch_bounds__(128, 2)
octo_gemm(const float* __restrict__ x, float* __restrict__ out)
{
    extern __shared__ __align__(16) float sm[];
    const uint32_t sbase = smem_u32(sm);
    const int tid   = threadIdx.x;
    const int wid   = tid >> 5;
    const int lane  = tid & 31;
    const int warpM = wid & 1;        // 2 warps over M (64 rows each)
    const int warpN = wid >> 1;       // 2 warps over N (64 cols each)
    const int tig   = lane & 3;       // thread-in-group (k)
    const int grp   = lane >> 2;      // group (m/n row)

    const int ntile = blockIdx.x;           // 0..7  == output head i
    const int mt_   = blockIdx.y;           // 0..255
    const int b     = mt_ >> 5;
    const int t0    = (mt_ & 31) << 7;

    const float* wgf = (const float*)g_WG;

    // ---- stage loader: A (XOR-swizzled) + B (fragment-order, contiguous) ----
    auto loadStage = [&](int kt, int slot) {
        const int j  = kt >> 2;
        const int d0 = (kt & 3) << 5;
        const float* xa = x + ((((size_t)(b * 8 + j)) * 4096 + t0) << 7) + d0;
        const uint32_t abase = sbase + slot * STAGE_BYTES;
        #pragma unroll
        for (int q = 0; q < 8; ++q) {
            const int c  = q * 128 + tid;
            const int m  = c >> 3;
            const int k4 = c & 7;
            cp16(abase + m * 128 + ((k4 ^ (m & 7)) << 4),
                 xa + (size_t)m * 128 + k4 * 4);
        }
        const uint32_t bbase = abase + 16384;
        #pragma unroll
        for (int ks = 0; ks < 4; ++ks) {
            #pragma unroll
            for (int h = 0; h < 2; ++h) {
                const int c = h * 128 + tid;   // 0..255 chunks of 16B = 4KB
                cp16(bbase + ks * 4096 + c * 16,
                     wgf + (((size_t)(kt * 4 + ks) * 128 + ntile * 16) << 6) + c * 4);
            }
        }
        cp_commit();
    };

    float acc[4][8][4];
    #pragma unroll
    for (int a = 0; a < 4; ++a)
        #pragma unroll
        for (int c = 0; c < 8; ++c)
            #pragma unroll
            for (int q = 0; q < 4; ++q) acc[a][c][q] = 0.0f;

    loadStage(0, 0);
    loadStage(1, 1);

    // Per-thread invariant address pieces.
    // ldmatrix lane roles: lanes 0-7/8-15/16-23/24-31 address matrices
    // r0..r3 = (rows0-7,k0-3)/(rows8-15,k0-3)/(rows0-7,k4-7)/(rows8-15,k4-7)
    //        = tf32 A fragment (a0,a1,a2,a3).
    const uint32_t lrow    = (uint32_t)(((lane >> 3) & 1) * 8 + (lane & 7));
    const uint32_t colhalf = (uint32_t)(lane >> 4);       // 0/1 -> k 0-3 / 4-7
    const uint32_t swz7    = (uint32_t)(lane & 7);        // == addressed row & 7
    const uint32_t a_lm    = (uint32_t)((warpM * 64 + lrow) * 128);
    const uint32_t b_thread = (uint32_t)(lane * 8);

    #pragma unroll 1
    for (int kt = 0; kt < KT; ++kt) {
        asm volatile("cp.async.wait_group 1;" ::: "memory");
        __syncthreads();
        const int nkt = kt + STAGES - 1;
        if (nkt < KT) loadStage(nkt, nkt % 3);   // slot (kt-1)%3, barrier-free
        else          cp_commit();               // keep group idx == chunk idx

        const int slot = kt % 3;
        const uint32_t abase = sbase + slot * STAGE_BYTES + a_lm;
        const uint32_t bbase = sbase + slot * STAGE_BYTES + 16384 + b_thread;

        // fragment double-buffer over ks
        uint32_t fa[2][4][4];
        uint32_t fb[2][8][2];
        auto loadFrags = [&](int ks, int buf) {
            const uint32_t xo = ((2u * ks + colhalf) ^ swz7) << 4;
            #pragma unroll
            for (int mt = 0; mt < 4; ++mt)
                ldsm_x4(fa[buf][mt], abase + mt * 2048 + xo);
            #pragma unroll
            for (int nt = 0; nt < 8; ++nt)
                lds64(fb[buf][nt][0], fb[buf][nt][1],
                      bbase + (uint32_t)((ks * 16 + warpN * 8 + nt) * 256));
        };

        loadFrags(0, 0);
        #pragma unroll
        for (int ks = 0; ks < 4; ++ks) {
            const int cur = ks & 1;
            if (ks < 3) loadFrags(ks + 1, cur ^ 1);
            #pragma unroll
            for (int mt = 0; mt < 4; ++mt)
                #pragma unroll
                for (int nt = 0; nt < 8; ++nt)
                    mma16n8k8(acc[mt][nt], fa[cur][mt], fb[cur][nt]);
        }
    }

    // ---- epilogue: registers -> gmem (head = ntile, e contiguous) ----
    const size_t obase = (((size_t)(b * 8 + ntile)) * 4096 + t0) << 7;
    #pragma unroll
    for (int mt = 0; mt < 4; ++mt) {
        const int r0 = warpM * 64 + mt * 16 + grp;
        #pragma unroll
        for (int nt = 0; nt < 8; ++nt) {
            const int e0 = warpN * 64 + nt * 8 + tig * 2;
            float2* p0 = (float2*)(out + obase + (size_t)r0 * 128 + e0);
            float2* p1 = (float2*)(out + obase + (size_t)(r0 + 8) * 128 + e0);
            *p0 = make_float2(acc[mt][nt][0], acc[mt][nt][1]);
            *p1 = make_float2(acc[mt][nt][2], acc[mt][nt][3]);
        }
    }
}

// ---------------- host ----------------
extern "C" void kernel_launch(void* const* d_in, const int* in_sizes, int n_in,
                              void* d_out, int out_size)
{
    const float* x    = (const float*)d_in[0];
    const float* W    = (const float*)d_in[1];
    const float* beta = (const float*)d_in[2];

    // 1) fold signs + beta into fragment-ordered combined weights (tf32 RN)
    octo_prep<<<4096, 256>>>(W, beta);

    // 2) GEMM: grid = (8 head-tiles, 256 row-tiles), 96 KB smem, 2 CTAs/SM.
    cudaFuncSetAttribute(octo_gemm, cudaFuncAttributeMaxDynamicSharedMemorySize,
                         (int)SMEM_TOTAL);
    dim3 grid(8, 256, 1);
    octo_gemm<<<grid, 128, SMEM_TOTAL>>>(x, (float*)d_out);
}